// round 5
// baseline (speedup 1.0000x reference)
#include <cuda_runtime.h>
#include <math.h>

#define BB 256
#define NCH 32
#define TT 2000
#define NTF 4
#define NSF 40
#define NSUB 20
#define TK 25
#define NCLS 4
#define NPAIR 210
#define NCHUNK 4
#define TC 500           // 4*500 = 2000
#define YS_STRIDE 504    // TC + 4 pad, multiple of 4 (16B alignment)
#define NSWEEP 6

typedef unsigned long long ull;

// Scratch: projected weights + per-chunk partial sums (full 20x20 + 20 means).
__device__ float g_Wc[128 * 20];               // [(g*32+c)*20 + s]
__device__ float g_part[NCHUNK][BB][420];      // [0..399]=sum y_i y_j, [400..419]=sum y_i

// ---- packed fp32x2 helpers ----
__device__ __forceinline__ void fma2(ull& d, ull a, ull b) {
    asm("fma.rn.f32x2 %0, %1, %2, %0;" : "+l"(d) : "l"(a), "l"(b));
}
__device__ __forceinline__ ull pack2(float lo, float hi) {
    ull r; asm("mov.b64 %0, {%1, %2};" : "=l"(r) : "f"(lo), "f"(hi)); return r;
}
__device__ __forceinline__ float2 unpack2(ull v) {
    float2 f; asm("mov.b64 {%0, %1}, %2;" : "=f"(f.x), "=f"(f.y) : "l"(v)); return f;
}

// ---------------------------------------------------------------------------
// Wc[s,g,c] = sum_f W_bimap[s,f] * conv2_w[f,g,c]  (biases cancel in cov)
// ---------------------------------------------------------------------------
__global__ void prep_kernel(const float* __restrict__ conv2_w,
                            const float* __restrict__ W_bimap) {
    int idx = blockIdx.x * blockDim.x + threadIdx.x;
    if (idx < 128 * 20) {
        int s = idx % 20, gc = idx / 20;
        float acc = 0.f;
        #pragma unroll 8
        for (int f = 0; f < NSF; ++f)
            acc += W_bimap[s * NSF + f] * conv2_w[f * 128 + gc];
        g_Wc[gc * 20 + s] = acc;
    }
}

// ---------------------------------------------------------------------------
// Fused conv1 (window straight from global, reflect only at tensor edges) ->
// 20-dim projection -> tiled covariance partials.
// One block per (chunk, batch); 4 consecutive t per thread.
// ---------------------------------------------------------------------------
__global__ void __launch_bounds__(128)
conv_cov_kernel(const float* __restrict__ x, const float* __restrict__ w1) {
    extern __shared__ float smem[];
    float* ys  = smem;                      // 20 * 504 = 10080
    float* wcs = ys + 20 * YS_STRIDE;       // 2560
    float* w2p = wcs + 2560;                // 8 slots * 28 = 224
    float* red = w2p + 224;                 // 25 tiles * 16 * 4 slices = 1600

    const int tid = threadIdx.x;
    const int chunk = blockIdx.x, b = blockIdx.y;
    const float* xb = x + (size_t)b * NCH * TT;

    for (int idx = tid; idx < 2560; idx += 128) wcs[idx] = g_Wc[idx];
    // packed conv1 weights: slot = phase*4+g, 13 pairs + zero pad (28 floats)
    if (tid < 104) {
        int phase = tid / 52, rem = tid % 52, g = rem / 13, i = rem % 13;
        float lo, hi;
        if (phase == 0) {
            lo = w1[g * TK + 2 * i];
            hi = (i < 12) ? w1[g * TK + 2 * i + 1] : 0.f;
        } else {
            lo = (i == 0) ? 0.f : w1[g * TK + 2 * i - 1];
            hi = w1[g * TK + 2 * i];
        }
        int base = (phase * 4 + g) * 28 + 2 * i;
        w2p[base] = lo; w2p[base + 1] = hi;
    }
    if (tid >= 104 && tid < 120) {
        int s = tid - 104;
        w2p[(s >> 1) * 28 + 26 + (s & 1)] = 0.f;
    }
    __syncthreads();

    // ---- conv + projection: thread -> t = tg..tg+3 ----
    if (tid < 125) {
        const int tl = 4 * tid;                 // local t in [0, 500)
        const int tg = chunk * TC + tl;         // global t
        const bool fast = (tg >= 12) && (tg <= TT - 16);
        ull accA[10], accB[10], accC[10], accD[10];
        #pragma unroll
        for (int q = 0; q < 10; ++q) { accA[q]=0; accB[q]=0; accC[q]=0; accD[q]=0; }

        const ull* w2 = (const ull*)w2p;        // [slot*14 + i]

        for (int c = 0; c < NCH; ++c) {
            // window x[c, tg-12 .. tg+15] -> 14 packed pairs (registers)
            ull win[14];
            if (fast) {
                const float4* p = (const float4*)(xb + c * TT + tg - 12); // 16B aligned
                #pragma unroll
                for (int i = 0; i < 7; ++i) {
                    float4 v = p[i];
                    win[2 * i]     = pack2(v.x, v.y);
                    win[2 * i + 1] = pack2(v.z, v.w);
                }
            } else {
                float fw[28];
                #pragma unroll
                for (int j = 0; j < 28; ++j) {
                    int gi = tg - 12 + j;
                    if (gi < 0) gi = -gi;
                    if (gi >= TT) gi = 2 * TT - 2 - gi;
                    fw[j] = xb[c * TT + gi];
                }
                #pragma unroll
                for (int i = 0; i < 14; ++i) win[i] = pack2(fw[2 * i], fw[2 * i + 1]);
            }

            #pragma unroll
            for (int g = 0; g < NTF; ++g) {
                ull sA = 0, sB = 0, sC = 0, sD = 0;
                #pragma unroll
                for (int i = 0; i < 13; ++i) {
                    ull wa = w2[g * 14 + i], wb = w2[(4 + g) * 14 + i]; // broadcast LDS
                    fma2(sA, win[i],     wa);   // h1[g,c,t]
                    fma2(sB, win[i],     wb);   // h1[g,c,t+1]
                    fma2(sC, win[i + 1], wa);   // h1[g,c,t+2]
                    fma2(sD, win[i + 1], wb);   // h1[g,c,t+3]
                }
                float2 fa = unpack2(sA), fb = unpack2(sB);
                float2 fc = unpack2(sC), fd = unpack2(sD);
                ull pa = pack2(fa.x + fa.y, fa.x + fa.y);
                ull pb = pack2(fb.x + fb.y, fb.x + fb.y);
                ull pc = pack2(fc.x + fc.y, fc.x + fc.y);
                ull pd = pack2(fd.x + fd.y, fd.x + fd.y);
                const ull* wv = (const ull*)&wcs[(g * 32 + c) * 20];   // broadcast LDS
                #pragma unroll
                for (int q = 0; q < 10; ++q) {
                    ull w = wv[q];
                    fma2(accA[q], w, pa);
                    fma2(accB[q], w, pb);
                    fma2(accC[q], w, pc);
                    fma2(accD[q], w, pd);
                }
            }
        }
        #pragma unroll
        for (int q = 0; q < 10; ++q) {
            float2 a = unpack2(accA[q]), bb2 = unpack2(accB[q]);
            float2 cc = unpack2(accC[q]), dd = unpack2(accD[q]);
            *(float4*)&ys[(2 * q)     * YS_STRIDE + tl] = make_float4(a.x, bb2.x, cc.x, dd.x);
            *(float4*)&ys[(2 * q + 1) * YS_STRIDE + tl] = make_float4(a.y, bb2.y, cc.y, dd.y);
        }
    }
    __syncthreads();

    // ---- covariance: 25 4x4-tiles x 4 t-slices (100 threads) + 20 means ----
    if (tid < 100) {
        const int tile = tid >> 2, slice = tid & 3;
        const int i0 = (tile / 5) * 4, j0 = (tile % 5) * 4;
        ull acc[16];
        #pragma unroll
        for (int e = 0; e < 16; ++e) acc[e] = 0;
        for (int t4 = slice; t4 < TC / 4; t4 += 4) {
            ull ri[4][2], rj[4][2];
            #pragma unroll
            for (int a = 0; a < 4; ++a) {
                const ull* pi = (const ull*)&ys[(i0 + a) * YS_STRIDE + 4 * t4];
                const ull* pj = (const ull*)&ys[(j0 + a) * YS_STRIDE + 4 * t4];
                ri[a][0] = pi[0]; ri[a][1] = pi[1];
                rj[a][0] = pj[0]; rj[a][1] = pj[1];
            }
            #pragma unroll
            for (int a = 0; a < 4; ++a)
                #pragma unroll
                for (int d = 0; d < 4; ++d) {
                    fma2(acc[a * 4 + d], ri[a][0], rj[d][0]);
                    fma2(acc[a * 4 + d], ri[a][1], rj[d][1]);
                }
        }
        #pragma unroll
        for (int e = 0; e < 16; ++e) {
            float2 f = unpack2(acc[e]);
            red[tile * 64 + e * 4 + slice] = f.x + f.y;
        }
    } else if (tid < 120) {
        const int r = tid - 100;
        const ull ones = pack2(1.f, 1.f);
        ull acc = 0;
        const ull* pr = (const ull*)&ys[r * YS_STRIDE];
        for (int t2 = 0; t2 < TC / 2; ++t2) fma2(acc, pr[t2], ones);
        float2 f = unpack2(acc);
        g_part[chunk][b][400 + r] = f.x + f.y;
    }
    __syncthreads();

    for (int p = tid; p < 400; p += 128) {
        int i = p / 20, j = p % 20;
        int tile = (i / 4) * 5 + (j / 4);
        int e = (i % 4) * 4 + (j % 4);
        const float* rp = &red[tile * 64 + e * 4];
        g_part[chunk][b][p] = rp[0] + rp[1] + rp[2] + rp[3];
    }
}

// ---------------------------------------------------------------------------
// Per-batch: assemble S, parallel-order Jacobi, matrix log, classifier.
// ---------------------------------------------------------------------------
__global__ void eig_kernel(const float* __restrict__ clf_w,
                           const float* __restrict__ clf_b,
                           float* __restrict__ out) {
    __shared__ float S[20][21];
    __shared__ float U[20][21];
    __shared__ float m[20], lw[20];
    __shared__ float cs[10], sn[10];
    __shared__ int   pa[10], qa[10];

    const int lane = threadIdx.x;
    const int b = blockIdx.x;

    if (lane < 20) {
        float acc = 0.f;
        #pragma unroll
        for (int ch = 0; ch < NCHUNK; ++ch) acc += g_part[ch][b][400 + lane];
        m[lane] = acc;
    }
    __syncwarp();

    for (int p = lane; p < 400; p += 32) {
        float acc = 0.f;
        #pragma unroll
        for (int ch = 0; ch < NCHUNK; ++ch) acc += g_part[ch][b][p];
        int i = p / 20, j = p % 20;
        S[i][j] = (acc - m[i] * m[j] * (1.0f / TT)) * (1.0f / (TT - 1));
    }
    for (int idx = lane; idx < 400; idx += 32) {
        int i = idx / 20, j = idx % 20;
        U[i][j] = (i == j) ? 1.f : 0.f;
    }
    __syncwarp();

    for (int sweep = 0; sweep < NSWEEP; ++sweep) {
        for (int r = 0; r < 19; ++r) {
            if (lane < 10) {
                int p = (lane == 0) ? 0 : 1 + ((lane - 1 + r) % 19);
                int q = 1 + ((18 - lane + r) % 19);
                float app = S[p][p], aqq = S[q][q], apq = S[p][q];
                float c = 1.f, s = 0.f;
                if (fabsf(apq) > 1e-12f) {
                    float tau = __fdividef(aqq - app, 2.f * apq);
                    float t = copysignf(__fdividef(1.f, fabsf(tau) + __fsqrt_rn(1.f + tau * tau)), tau);
                    c = rsqrtf(1.f + t * t);
                    s = t * c;
                }
                cs[lane] = c; sn[lane] = s; pa[lane] = p; qa[lane] = q;
            }
            __syncwarp();
            #pragma unroll
            for (int it = 0; it < 7; ++it) {
                int idx = lane + it * 32;
                if (idx < 200) {
                    int pr = idx / 20, k = idx - pr * 20;
                    int p = pa[pr], q = qa[pr];
                    float c = cs[pr], s = sn[pr];
                    float akp = S[k][p], akq = S[k][q];
                    S[k][p] = c * akp - s * akq;
                    S[k][q] = s * akp + c * akq;
                    float ukp = U[k][p], ukq = U[k][q];
                    U[k][p] = c * ukp - s * ukq;
                    U[k][q] = s * ukp + c * ukq;
                }
            }
            __syncwarp();
            #pragma unroll
            for (int it = 0; it < 7; ++it) {
                int idx = lane + it * 32;
                if (idx < 200) {
                    int pr = idx / 20, k = idx - pr * 20;
                    int p = pa[pr], q = qa[pr];
                    float c = cs[pr], s = sn[pr];
                    float apk = S[p][k], aqk = S[q][k];
                    S[p][k] = c * apk - s * aqk;
                    S[q][k] = s * apk + c * aqk;
                }
            }
            __syncwarp();
        }
    }

    if (lane < 20) lw[lane] = logf(fmaxf(S[lane][lane], 1e-4f));
    __syncwarp();

    float o0 = 0.f, o1 = 0.f, o2 = 0.f, o3 = 0.f;
    const float SQ2 = 1.41421356237309515f;
    for (int p = lane; p < NPAIR; p += 32) {
        int i = 0, rem = p;
        while (rem >= 20 - i) { rem -= 20 - i; ++i; }
        int j = i + rem;
        float L = 0.f;
        #pragma unroll
        for (int mm = 0; mm < 20; ++mm) L += U[i][mm] * lw[mm] * U[j][mm];
        float z = L * ((i == j) ? 1.f : SQ2);
        o0 += z * clf_w[0 * NPAIR + p];
        o1 += z * clf_w[1 * NPAIR + p];
        o2 += z * clf_w[2 * NPAIR + p];
        o3 += z * clf_w[3 * NPAIR + p];
    }
    #pragma unroll
    for (int off = 16; off; off >>= 1) {
        o0 += __shfl_down_sync(0xffffffffu, o0, off);
        o1 += __shfl_down_sync(0xffffffffu, o1, off);
        o2 += __shfl_down_sync(0xffffffffu, o2, off);
        o3 += __shfl_down_sync(0xffffffffu, o3, off);
    }
    if (lane == 0) {
        out[b * 4 + 0] = o0 + clf_b[0];
        out[b * 4 + 1] = o1 + clf_b[1];
        out[b * 4 + 2] = o2 + clf_b[2];
        out[b * 4 + 3] = o3 + clf_b[3];
    }
}

// ---------------------------------------------------------------------------
extern "C" void kernel_launch(void* const* d_in, const int* in_sizes, int n_in,
                              void* d_out, int out_size) {
    const float* x       = (const float*)d_in[0];
    const float* conv1_w = (const float*)d_in[1];
    const float* conv2_w = (const float*)d_in[3];
    const float* W_bimap = (const float*)d_in[5];
    const float* clf_w   = (const float*)d_in[6];
    const float* clf_b   = (const float*)d_in[7];
    float* out = (float*)d_out;

    size_t smem_bytes = (size_t)(20 * YS_STRIDE + 2560 + 224 + 1600) * sizeof(float);
    cudaFuncSetAttribute(conv_cov_kernel,
                         cudaFuncAttributeMaxDynamicSharedMemorySize,
                         (int)smem_bytes);

    prep_kernel<<<10, 256>>>(conv2_w, W_bimap);
    conv_cov_kernel<<<dim3(NCHUNK, BB), 128, smem_bytes>>>(x, conv1_w);
    eig_kernel<<<BB, 32>>>(clf_w, clf_b, out);
}

// round 6
// speedup vs baseline: 1.1738x; 1.1738x over previous
#include <cuda_runtime.h>
#include <math.h>

#define BB 256
#define NCH 32
#define TT 2000
#define NTF 4
#define NSF 40
#define NSUB 20
#define TK 25
#define NPAIR 210
#define NCHUNK 8
#define TC 250
#define ZW 280           // zs width: 35*8 (covers 274 needed cols)
#define YSS 258          // ys stride (padded, even, bank-decorrelated)
#define NSWEEP 6

typedef unsigned long long ull;

// Scratch: projected weights + per-chunk partial sums.
__device__ float g_W2[80 * 32];                // [sg*32 + c], sg = s*4 + g
__device__ float g_part[NCHUNK][BB][420];      // [0..399]=sum y_i y_j, [400..419]=sum y_i

__device__ __forceinline__ void fma2(ull& d, ull a, ull b) {
    asm("fma.rn.f32x2 %0, %1, %2, %0;" : "+l"(d) : "l"(a), "l"(b));
}
__device__ __forceinline__ ull pack2(float lo, float hi) {
    ull r; asm("mov.b64 %0, {%1, %2};" : "=l"(r) : "f"(lo), "f"(hi)); return r;
}
__device__ __forceinline__ float2 unpack2(ull v) {
    float2 f; asm("mov.b64 {%0, %1}, %2;" : "=f"(f.x), "=f"(f.y) : "l"(v)); return f;
}

// ---------------------------------------------------------------------------
// W2[sg=s*4+g][c] = sum_f W_bimap[s,f] * conv2_w[f,g,c]  (biases cancel in cov)
// ---------------------------------------------------------------------------
__global__ void prep_kernel(const float* __restrict__ conv2_w,
                            const float* __restrict__ W_bimap) {
    int idx = blockIdx.x * blockDim.x + threadIdx.x;
    if (idx < 80 * 32) {
        int sg = idx / 32, c = idx % 32;
        int s = sg / 4, g = sg % 4;
        float acc = 0.f;
        #pragma unroll 8
        for (int f = 0; f < NSF; ++f)
            acc += W_bimap[s * NSF + f] * conv2_w[f * 128 + g * 32 + c];
        g_W2[sg * 32 + c] = acc;
    }
}

// ---------------------------------------------------------------------------
// Fused: per slab (4 s values = 16 sg rows):
//   stage A: z[sg, tau] = sum_c W2[sg,c]*x[c, t0-12+tau]  (GEMM, x from L2)
//   stage B: y[s, t]    = sum_g sum_k w1[g,k]*z[s*4+g, t+k]
// then tiled covariance partials. One block per (chunk, batch).
// ---------------------------------------------------------------------------
__global__ void __launch_bounds__(128, 4)
conv_cov_kernel(const float* __restrict__ x, const float* __restrict__ w1) {
    extern __shared__ float smem[];
    float* zs  = smem;                      // 16 * 280 = 4480 (aliased by red later)
    float* ys  = zs + 16 * ZW;              // 20 * 258 = 5160
    float* w2s = ys + 20 * YSS;             // 2560
    float* w1p = w2s + 2560;                // 8 slots * 28 = 224
    float* red = zs;                        // cov reduction (1600 <= 4480)

    const int tid = threadIdx.x;
    const int chunk = blockIdx.x, b = blockIdx.y;
    const int t0 = chunk * TC;
    const bool edge = (chunk == 0) || (chunk == NCHUNK - 1);
    const float* __restrict__ xb = x + (size_t)b * NCH * TT;

    for (int idx = tid; idx < 2560; idx += 128) w2s[idx] = g_W2[idx];
    // packed conv1 weights: slot = phase*4+g, 13 pairs + zero pad (28 floats)
    if (tid < 104) {
        int phase = tid / 52, rem = tid % 52, g = rem / 13, i = rem % 13;
        float lo, hi;
        if (phase == 0) {
            lo = w1[g * TK + 2 * i];
            hi = (i < 12) ? w1[g * TK + 2 * i + 1] : 0.f;
        } else {
            lo = (i == 0) ? 0.f : w1[g * TK + 2 * i - 1];
            hi = w1[g * TK + 2 * i];
        }
        int base = (phase * 4 + g) * 28 + 2 * i;
        w1p[base] = lo; w1p[base + 1] = hi;
    }
    if (tid >= 104 && tid < 120) {
        int s = tid - 104;
        w1p[(s >> 1) * 28 + 26 + (s & 1)] = 0.f;
    }
    __syncthreads();

    const ull* wp = (const ull*)w1p;        // [slot*14 + i]

    for (int slb = 0; slb < 5; ++slb) {
        // ---- stage A: compute zs[16][280] for sg = slb*16 .. slb*16+15 ----
        for (int it = tid; it < 140; it += 128) {
            const int ti = it % 35, sq = it / 35;   // sq = s_loc (0..3)
            const int tau0 = ti * 8;
            const int gt = t0 - 12 + tau0;          // even
            ull acc[4][4];
            #pragma unroll
            for (int q = 0; q < 4; ++q)
                #pragma unroll
                for (int p = 0; p < 4; ++p) acc[q][p] = 0;

            const int wrow = (slb * 16 + sq * 4) * 32;  // + q*32 + c

            if (!edge) {
                #pragma unroll 2
                for (int c = 0; c < NCH; ++c) {
                    const ull* xp = (const ull*)(xb + c * TT + gt); // 8B aligned
                    ull xv0 = xp[0], xv1 = xp[1], xv2 = xp[2], xv3 = xp[3];
                    #pragma unroll
                    for (int q = 0; q < 4; ++q) {
                        float w = w2s[wrow + q * 32 + c];
                        ull wd = pack2(w, w);
                        fma2(acc[q][0], xv0, wd);
                        fma2(acc[q][1], xv1, wd);
                        fma2(acc[q][2], xv2, wd);
                        fma2(acc[q][3], xv3, wd);
                    }
                }
            } else {
                for (int c = 0; c < NCH; ++c) {
                    float tmp[8];
                    #pragma unroll
                    for (int j = 0; j < 8; ++j) {
                        int gi = gt + j;
                        if (gi < 0) gi = -gi;
                        if (gi >= TT) gi = 2 * TT - 2 - gi;
                        tmp[j] = xb[c * TT + gi];
                    }
                    ull xv0 = pack2(tmp[0], tmp[1]), xv1 = pack2(tmp[2], tmp[3]);
                    ull xv2 = pack2(tmp[4], tmp[5]), xv3 = pack2(tmp[6], tmp[7]);
                    #pragma unroll
                    for (int q = 0; q < 4; ++q) {
                        float w = w2s[wrow + q * 32 + c];
                        ull wd = pack2(w, w);
                        fma2(acc[q][0], xv0, wd);
                        fma2(acc[q][1], xv1, wd);
                        fma2(acc[q][2], xv2, wd);
                        fma2(acc[q][3], xv3, wd);
                    }
                }
            }
            #pragma unroll
            for (int q = 0; q < 4; ++q)
                #pragma unroll
                for (int p = 0; p < 4; ++p)
                    *(ull*)&zs[(sq * 4 + q) * ZW + tau0 + 2 * p] = acc[q][p];
        }
        __syncthreads();

        // ---- stage B: y[s, tl..tl+7] for s = slb*4 + s_loc ----
        {
            const int s_loc = tid >> 5, ti = tid & 31;
            const int tl = ti * 8;                  // 0..248
            ull accP[8];
            #pragma unroll
            for (int o = 0; o < 8; ++o) accP[o] = 0;

            #pragma unroll
            for (int g = 0; g < 4; ++g) {
                const ull* zrow = (const ull*)&zs[(s_loc * 4 + g) * ZW + tl];
                ull win[16];
                #pragma unroll
                for (int j = 0; j < 16; ++j) win[j] = zrow[j];
                #pragma unroll
                for (int i = 0; i < 13; ++i) {
                    ull wa = wp[g * 14 + i], wb = wp[(4 + g) * 14 + i]; // broadcast
                    #pragma unroll
                    for (int m = 0; m < 4; ++m) {
                        fma2(accP[2 * m],     win[m + i], wa);
                        fma2(accP[2 * m + 1], win[m + i], wb);
                    }
                }
            }
            const int s = slb * 4 + s_loc;
            #pragma unroll
            for (int m = 0; m < 4; ++m) {
                float2 e = unpack2(accP[2 * m]);
                float2 o = unpack2(accP[2 * m + 1]);
                *(float2*)&ys[s * YSS + tl + 2 * m] = make_float2(e.x + e.y, o.x + o.y);
            }
        }
        __syncthreads();  // zs reused next slab
    }

    // zero pad columns t = 250..255 (t4=62,63 touch them)
    if (tid < 120) {
        int s = tid / 6, col = 250 + tid % 6;
        ys[s * YSS + col] = 0.f;
    }
    __syncthreads();

    // ---- covariance: 25 4x4-tiles x 4 t-slices + 20 means ----
    if (tid < 100) {
        const int tile = tid >> 2, slice = tid & 3;
        const int i0 = (tile / 5) * 4, j0 = (tile % 5) * 4;
        ull acc[16];
        #pragma unroll
        for (int e = 0; e < 16; ++e) acc[e] = 0;
        for (int t4 = slice; t4 < 64; t4 += 4) {
            ull ri[4][2], rj[4][2];
            #pragma unroll
            for (int a = 0; a < 4; ++a) {
                const ull* pi = (const ull*)&ys[(i0 + a) * YSS + 4 * t4];
                const ull* pj = (const ull*)&ys[(j0 + a) * YSS + 4 * t4];
                ri[a][0] = pi[0]; ri[a][1] = pi[1];
                rj[a][0] = pj[0]; rj[a][1] = pj[1];
            }
            #pragma unroll
            for (int a = 0; a < 4; ++a)
                #pragma unroll
                for (int d = 0; d < 4; ++d) {
                    fma2(acc[a * 4 + d], ri[a][0], rj[d][0]);
                    fma2(acc[a * 4 + d], ri[a][1], rj[d][1]);
                }
        }
        #pragma unroll
        for (int e = 0; e < 16; ++e) {
            float2 f = unpack2(acc[e]);
            red[tile * 64 + e * 4 + slice] = f.x + f.y;
        }
    } else if (tid < 120) {
        const int r = tid - 100;
        const ull ones = pack2(1.f, 1.f);
        ull acc = 0;
        const ull* pr = (const ull*)&ys[r * YSS];
        for (int t2 = 0; t2 < 128; ++t2) fma2(acc, pr[t2], ones);
        float2 f = unpack2(acc);
        g_part[chunk][b][400 + r] = f.x + f.y;
    }
    __syncthreads();

    for (int p = tid; p < 400; p += 128) {
        int i = p / 20, j = p % 20;
        int tile = (i / 4) * 5 + (j / 4);
        int e = (i % 4) * 4 + (j % 4);
        const float* rp = &red[tile * 64 + e * 4];
        g_part[chunk][b][p] = rp[0] + rp[1] + rp[2] + rp[3];
    }
}

// ---------------------------------------------------------------------------
// Per-batch: assemble S, parallel-order Jacobi, matrix log, classifier.
// 64 threads (2 warps) to halve update-loop latency.
// ---------------------------------------------------------------------------
__global__ void __launch_bounds__(64)
eig_kernel(const float* __restrict__ clf_w,
           const float* __restrict__ clf_b,
           float* __restrict__ out) {
    __shared__ float S[20][21];
    __shared__ float U[20][21];
    __shared__ float m[20], lw[20];
    __shared__ float cs[10], sn[10];
    __shared__ int   pa[10], qa[10];

    const int tid = threadIdx.x;
    const int b = blockIdx.x;

    if (tid < 20) {
        float acc = 0.f;
        #pragma unroll
        for (int ch = 0; ch < NCHUNK; ++ch) acc += g_part[ch][b][400 + tid];
        m[tid] = acc;
    }
    __syncthreads();

    for (int p = tid; p < 400; p += 64) {
        float acc = 0.f;
        #pragma unroll
        for (int ch = 0; ch < NCHUNK; ++ch) acc += g_part[ch][b][p];
        int i = p / 20, j = p % 20;
        S[i][j] = (acc - m[i] * m[j] * (1.0f / TT)) * (1.0f / (TT - 1));
    }
    for (int idx = tid; idx < 400; idx += 64) {
        int i = idx / 20, j = idx % 20;
        U[i][j] = (i == j) ? 1.f : 0.f;
    }
    __syncthreads();

    for (int sweep = 0; sweep < NSWEEP; ++sweep) {
        for (int r = 0; r < 19; ++r) {
            if (tid < 10) {
                int p = (tid == 0) ? 0 : 1 + ((tid - 1 + r) % 19);
                int q = 1 + ((18 - tid + r) % 19);
                float app = S[p][p], aqq = S[q][q], apq = S[p][q];
                float c = 1.f, s = 0.f;
                if (fabsf(apq) > 1e-12f) {
                    float tau = __fdividef(aqq - app, 2.f * apq);
                    float t = copysignf(__fdividef(1.f, fabsf(tau) + __fsqrt_rn(1.f + tau * tau)), tau);
                    c = rsqrtf(1.f + t * t);
                    s = t * c;
                }
                cs[tid] = c; sn[tid] = s; pa[tid] = p; qa[tid] = q;
            }
            __syncthreads();
            #pragma unroll
            for (int it = 0; it < 4; ++it) {
                int idx = tid + it * 64;
                if (idx < 200) {
                    int pr = idx / 20, k = idx - pr * 20;
                    int p = pa[pr], q = qa[pr];
                    float c = cs[pr], s = sn[pr];
                    float akp = S[k][p], akq = S[k][q];
                    S[k][p] = c * akp - s * akq;
                    S[k][q] = s * akp + c * akq;
                    float ukp = U[k][p], ukq = U[k][q];
                    U[k][p] = c * ukp - s * ukq;
                    U[k][q] = s * ukp + c * ukq;
                }
            }
            __syncthreads();
            #pragma unroll
            for (int it = 0; it < 4; ++it) {
                int idx = tid + it * 64;
                if (idx < 200) {
                    int pr = idx / 20, k = idx - pr * 20;
                    int p = pa[pr], q = qa[pr];
                    float c = cs[pr], s = sn[pr];
                    float apk = S[p][k], aqk = S[q][k];
                    S[p][k] = c * apk - s * aqk;
                    S[q][k] = s * apk + c * aqk;
                }
            }
            __syncthreads();
        }
    }

    if (tid < 20) lw[tid] = logf(fmaxf(S[tid][tid], 1e-4f));
    __syncthreads();

    if (tid < 32) {
        float o0 = 0.f, o1 = 0.f, o2 = 0.f, o3 = 0.f;
        const float SQ2 = 1.41421356237309515f;
        for (int p = tid; p < NPAIR; p += 32) {
            int i = 0, rem = p;
            while (rem >= 20 - i) { rem -= 20 - i; ++i; }
            int j = i + rem;
            float L = 0.f;
            #pragma unroll
            for (int mm = 0; mm < 20; ++mm) L += U[i][mm] * lw[mm] * U[j][mm];
            float z = L * ((i == j) ? 1.f : SQ2);
            o0 += z * clf_w[0 * NPAIR + p];
            o1 += z * clf_w[1 * NPAIR + p];
            o2 += z * clf_w[2 * NPAIR + p];
            o3 += z * clf_w[3 * NPAIR + p];
        }
        #pragma unroll
        for (int off = 16; off; off >>= 1) {
            o0 += __shfl_down_sync(0xffffffffu, o0, off);
            o1 += __shfl_down_sync(0xffffffffu, o1, off);
            o2 += __shfl_down_sync(0xffffffffu, o2, off);
            o3 += __shfl_down_sync(0xffffffffu, o3, off);
        }
        if (tid == 0) {
            out[b * 4 + 0] = o0 + clf_b[0];
            out[b * 4 + 1] = o1 + clf_b[1];
            out[b * 4 + 2] = o2 + clf_b[2];
            out[b * 4 + 3] = o3 + clf_b[3];
        }
    }
}

// ---------------------------------------------------------------------------
extern "C" void kernel_launch(void* const* d_in, const int* in_sizes, int n_in,
                              void* d_out, int out_size) {
    const float* x       = (const float*)d_in[0];
    const float* conv1_w = (const float*)d_in[1];
    const float* conv2_w = (const float*)d_in[3];
    const float* W_bimap = (const float*)d_in[5];
    const float* clf_w   = (const float*)d_in[6];
    const float* clf_b   = (const float*)d_in[7];
    float* out = (float*)d_out;

    size_t smem_bytes = (size_t)(16 * ZW + 20 * YSS + 2560 + 224) * sizeof(float);
    cudaFuncSetAttribute(conv_cov_kernel,
                         cudaFuncAttributeMaxDynamicSharedMemorySize,
                         (int)smem_bytes);

    prep_kernel<<<10, 256>>>(conv2_w, W_bimap);
    conv_cov_kernel<<<dim3(NCHUNK, BB), 128, smem_bytes>>>(x, conv1_w);
    eig_kernel<<<BB, 64>>>(clf_w, clf_b, out);
}

// round 7
// speedup vs baseline: 1.8921x; 1.6119x over previous
#include <cuda_runtime.h>
#include <math.h>

#define BB 256
#define NCH 32
#define TT 2000
#define NTF 4
#define NSF 40
#define NSUB 20
#define TK 25
#define NPAIR 210
#define NCHUNK 8
#define TC 250
#define ZW 288           // z row width: covers tau 0..287 (need 0..279)
#define YSS 258
#define NSWEEP 6

typedef unsigned long long ull;

// Static scratch (no runtime allocation allowed)
__device__ float g_W2T[32 * 80];                       // [c*80 + sg]
__device__ float g_z[(size_t)BB * NCHUNK * 80 * ZW];   // 188.7 MB
__device__ float g_part[NCHUNK][BB][420];

__device__ __forceinline__ void fma2(ull& d, ull a, ull b) {
    asm("fma.rn.f32x2 %0, %1, %2, %0;" : "+l"(d) : "l"(a), "l"(b));
}
__device__ __forceinline__ ull pack2(float lo, float hi) {
    ull r; asm("mov.b64 %0, {%1, %2};" : "=l"(r) : "f"(lo), "f"(hi)); return r;
}
__device__ __forceinline__ float2 unpack2(ull v) {
    float2 f; asm("mov.b64 {%0, %1}, %2;" : "=f"(f.x), "=f"(f.y) : "l"(v)); return f;
}

// ---------------------------------------------------------------------------
// W2T[c][sg] = sum_f W_bimap[s,f] * conv2_w[f,g,c],  sg = s*4+g
// ---------------------------------------------------------------------------
__global__ void prep_kernel(const float* __restrict__ conv2_w,
                            const float* __restrict__ W_bimap) {
    int idx = blockIdx.x * blockDim.x + threadIdx.x;
    if (idx < 2560) {
        int c = idx / 80, sg = idx % 80;
        int s = sg / 4, g = sg % 4;
        float acc = 0.f;
        #pragma unroll 8
        for (int f = 0; f < NSF; ++f)
            acc += W_bimap[s * NSF + f] * conv2_w[f * 128 + g * 32 + c];
        g_W2T[c * 80 + sg] = acc;
    }
}

// ---------------------------------------------------------------------------
// Kernel A: z[sg, tau] = sum_c W2[sg,c] * x[c, t0 - 12 + tau]   (GEMM)
// x tile staged in smem; thread computes 4 sg x 12 tau; warp = one sg-group.
// ---------------------------------------------------------------------------
__global__ void __launch_bounds__(128)
gemm_kernel(const float* __restrict__ x) {
    __shared__ float xs[32][ZW];     // 36.9 KB
    __shared__ float w2t[32][80];    // 10.2 KB

    const int tid = threadIdx.x;
    const int chunk = blockIdx.x, b = blockIdx.y;
    const int t0 = chunk * TC;
    const float* __restrict__ xb = x + (size_t)b * NCH * TT;

    for (int idx = tid; idx < 32 * ZW; idx += 128) {
        int c = idx / ZW, tt = idx % ZW;
        int gi = t0 - 12 + tt;
        if (gi < 0) gi = -gi;
        if (gi >= TT) gi = 2 * TT - 2 - gi;
        xs[c][tt] = xb[c * TT + gi];
    }
    for (int idx = tid; idx < 2560; idx += 128)
        ((float*)w2t)[idx] = g_W2T[idx];
    __syncthreads();

    const int warp = tid >> 5, lane = tid & 31;
    if (lane < 24) {
        const int tau0 = lane * 12;
        float* zbase = &g_z[((size_t)(b * NCHUNK + chunk) * 80) * ZW];

        #pragma unroll 1
        for (int pass = 0; pass < 5; ++pass) {
            const int sg0 = (pass * 4 + warp) * 4;
            ull acc[4][6];
            #pragma unroll
            for (int q = 0; q < 4; ++q)
                #pragma unroll
                for (int p = 0; p < 6; ++p) acc[q][p] = 0;

            #pragma unroll 2
            for (int c = 0; c < NCH; ++c) {
                const float4* xp = (const float4*)&xs[c][tau0];
                float4 v0 = xp[0], v1 = xp[1], v2 = xp[2];
                ull xv[6];
                xv[0] = pack2(v0.x, v0.y); xv[1] = pack2(v0.z, v0.w);
                xv[2] = pack2(v1.x, v1.y); xv[3] = pack2(v1.z, v1.w);
                xv[4] = pack2(v2.x, v2.y); xv[5] = pack2(v2.z, v2.w);
                float4 wq = *(const float4*)&w2t[c][sg0];   // broadcast
                ull wd[4];
                wd[0] = pack2(wq.x, wq.x); wd[1] = pack2(wq.y, wq.y);
                wd[2] = pack2(wq.z, wq.z); wd[3] = pack2(wq.w, wq.w);
                #pragma unroll
                for (int q = 0; q < 4; ++q)
                    #pragma unroll
                    for (int p = 0; p < 6; ++p)
                        fma2(acc[q][p], xv[p], wd[q]);
            }
            #pragma unroll
            for (int q = 0; q < 4; ++q) {
                float* zr = zbase + (size_t)(sg0 + q) * ZW + tau0;
                #pragma unroll
                for (int p = 0; p < 3; ++p) {
                    float2 lo = unpack2(acc[q][2 * p]);
                    float2 hi = unpack2(acc[q][2 * p + 1]);
                    *(float4*)(zr + 4 * p) = make_float4(lo.x, lo.y, hi.x, hi.y);
                }
            }
        }
    }
}

// ---------------------------------------------------------------------------
// Kernel B: y[s,t] = sum_g sum_k w1[g,k] z[s*4+g, t+k]; then covariance.
// z slabs (16 rows) staged via coalesced LDG; phase-packed conv.
// ---------------------------------------------------------------------------
__global__ void __launch_bounds__(128)
conv_cov_kernel(const float* __restrict__ w1) {
    __shared__ float zs[16 * ZW];    // 18.4 KB (aliased by red after slabs)
    __shared__ float ys[20 * YSS];   // 20.6 KB
    __shared__ float w1p[224];
    float* red = zs;                 // 1600 floats <= 4608

    const int tid = threadIdx.x;
    const int chunk = blockIdx.x, b = blockIdx.y;
    const float* zbase = &g_z[((size_t)(b * NCHUNK + chunk) * 80) * ZW];

    // packed conv1 weights: slot = phase*4+g, 13 pairs + zero pad (28 floats)
    if (tid < 104) {
        int phase = tid / 52, rem = tid % 52, g = rem / 13, i = rem % 13;
        float lo, hi;
        if (phase == 0) {
            lo = w1[g * TK + 2 * i];
            hi = (i < 12) ? w1[g * TK + 2 * i + 1] : 0.f;
        } else {
            lo = (i == 0) ? 0.f : w1[g * TK + 2 * i - 1];
            hi = w1[g * TK + 2 * i];
        }
        int base = (phase * 4 + g) * 28 + 2 * i;
        w1p[base] = lo; w1p[base + 1] = hi;
    }
    if (tid >= 104 && tid < 120) {
        int s = tid - 104;
        w1p[(s >> 1) * 28 + 26 + (s & 1)] = 0.f;
    }
    __syncthreads();

    const ull* wp = (const ull*)w1p;

    for (int slb = 0; slb < 5; ++slb) {
        // stage z slab: rows slb*16 .. slb*16+15, coalesced float4 loads
        {
            const float4* src = (const float4*)(zbase + (size_t)slb * 16 * ZW);
            float4* dst = (float4*)zs;
            for (int i = tid; i < 16 * ZW / 4; i += 128) dst[i] = src[i];
        }
        __syncthreads();

        // phase-packed conv: thread -> (s_loc, 8 consecutive t)
        {
            const int s_loc = tid >> 5, ti = tid & 31;
            const int tl = ti * 8;                  // 0..248
            ull accP[8];
            #pragma unroll
            for (int o = 0; o < 8; ++o) accP[o] = 0;

            #pragma unroll
            for (int g = 0; g < 4; ++g) {
                const ull* zrow = (const ull*)&zs[(s_loc * 4 + g) * ZW + tl];
                ull win[16];
                #pragma unroll
                for (int j = 0; j < 16; ++j) win[j] = zrow[j];
                #pragma unroll
                for (int i = 0; i < 13; ++i) {
                    ull wa = wp[g * 14 + i], wb = wp[(4 + g) * 14 + i];
                    #pragma unroll
                    for (int m = 0; m < 4; ++m) {
                        fma2(accP[2 * m],     win[m + i], wa);
                        fma2(accP[2 * m + 1], win[m + i], wb);
                    }
                }
            }
            const int s = slb * 4 + s_loc;
            #pragma unroll
            for (int m = 0; m < 4; ++m) {
                float2 e = unpack2(accP[2 * m]);
                float2 o = unpack2(accP[2 * m + 1]);
                *(float2*)&ys[s * YSS + tl + 2 * m] = make_float2(e.x + e.y, o.x + o.y);
            }
        }
        __syncthreads();
    }

    // zero pad columns t = 250..255
    if (tid < 120) {
        int s = tid / 6, col = 250 + tid % 6;
        ys[s * YSS + col] = 0.f;
    }
    __syncthreads();

    // covariance: 25 4x4-tiles x 4 t-slices + 20 means
    if (tid < 100) {
        const int tile = tid >> 2, slice = tid & 3;
        const int i0 = (tile / 5) * 4, j0 = (tile % 5) * 4;
        ull acc[16];
        #pragma unroll
        for (int e = 0; e < 16; ++e) acc[e] = 0;
        for (int t4 = slice; t4 < 64; t4 += 4) {
            ull ri[4][2], rj[4][2];
            #pragma unroll
            for (int a = 0; a < 4; ++a) {
                const ull* pi = (const ull*)&ys[(i0 + a) * YSS + 4 * t4];
                const ull* pj = (const ull*)&ys[(j0 + a) * YSS + 4 * t4];
                ri[a][0] = pi[0]; ri[a][1] = pi[1];
                rj[a][0] = pj[0]; rj[a][1] = pj[1];
            }
            #pragma unroll
            for (int a = 0; a < 4; ++a)
                #pragma unroll
                for (int d = 0; d < 4; ++d) {
                    fma2(acc[a * 4 + d], ri[a][0], rj[d][0]);
                    fma2(acc[a * 4 + d], ri[a][1], rj[d][1]);
                }
        }
        #pragma unroll
        for (int e = 0; e < 16; ++e) {
            float2 f = unpack2(acc[e]);
            red[tile * 64 + e * 4 + slice] = f.x + f.y;
        }
    } else if (tid < 120) {
        const int r = tid - 100;
        const ull ones = pack2(1.f, 1.f);
        ull acc = 0;
        const ull* pr = (const ull*)&ys[r * YSS];
        for (int t2 = 0; t2 < 128; ++t2) fma2(acc, pr[t2], ones);
        float2 f = unpack2(acc);
        g_part[chunk][b][400 + r] = f.x + f.y;
    }
    __syncthreads();

    for (int p = tid; p < 400; p += 128) {
        int i = p / 20, j = p % 20;
        int tile = (i / 4) * 5 + (j / 4);
        int e = (i % 4) * 4 + (j % 4);
        const float* rp = &red[tile * 64 + e * 4];
        g_part[chunk][b][p] = rp[0] + rp[1] + rp[2] + rp[3];
    }
}

// ---------------------------------------------------------------------------
// Per-batch: assemble S, parallel-order Jacobi, matrix log, classifier.
// ---------------------------------------------------------------------------
__global__ void __launch_bounds__(64)
eig_kernel(const float* __restrict__ clf_w,
           const float* __restrict__ clf_b,
           float* __restrict__ out) {
    __shared__ float S[20][21];
    __shared__ float U[20][21];
    __shared__ float m[20], lw[20];
    __shared__ float cs[10], sn[10];
    __shared__ int   pa[10], qa[10];

    const int tid = threadIdx.x;
    const int b = blockIdx.x;

    if (tid < 20) {
        float acc = 0.f;
        #pragma unroll
        for (int ch = 0; ch < NCHUNK; ++ch) acc += g_part[ch][b][400 + tid];
        m[tid] = acc;
    }
    __syncthreads();

    for (int p = tid; p < 400; p += 64) {
        float acc = 0.f;
        #pragma unroll
        for (int ch = 0; ch < NCHUNK; ++ch) acc += g_part[ch][b][p];
        int i = p / 20, j = p % 20;
        S[i][j] = (acc - m[i] * m[j] * (1.0f / TT)) * (1.0f / (TT - 1));
    }
    for (int idx = tid; idx < 400; idx += 64) {
        int i = idx / 20, j = idx % 20;
        U[i][j] = (i == j) ? 1.f : 0.f;
    }
    __syncthreads();

    for (int sweep = 0; sweep < NSWEEP; ++sweep) {
        for (int r = 0; r < 19; ++r) {
            if (tid < 10) {
                int p = (tid == 0) ? 0 : 1 + ((tid - 1 + r) % 19);
                int q = 1 + ((18 - tid + r) % 19);
                float app = S[p][p], aqq = S[q][q], apq = S[p][q];
                float c = 1.f, s = 0.f;
                if (fabsf(apq) > 1e-12f) {
                    float tau = __fdividef(aqq - app, 2.f * apq);
                    float t = copysignf(__fdividef(1.f, fabsf(tau) + __fsqrt_rn(1.f + tau * tau)), tau);
                    c = rsqrtf(1.f + t * t);
                    s = t * c;
                }
                cs[tid] = c; sn[tid] = s; pa[tid] = p; qa[tid] = q;
            }
            __syncthreads();
            #pragma unroll
            for (int it = 0; it < 4; ++it) {
                int idx = tid + it * 64;
                if (idx < 200) {
                    int pr = idx / 20, k = idx - pr * 20;
                    int p = pa[pr], q = qa[pr];
                    float c = cs[pr], s = sn[pr];
                    float akp = S[k][p], akq = S[k][q];
                    S[k][p] = c * akp - s * akq;
                    S[k][q] = s * akp + c * akq;
                    float ukp = U[k][p], ukq = U[k][q];
                    U[k][p] = c * ukp - s * ukq;
                    U[k][q] = s * ukp + c * ukq;
                }
            }
            __syncthreads();
            #pragma unroll
            for (int it = 0; it < 4; ++it) {
                int idx = tid + it * 64;
                if (idx < 200) {
                    int pr = idx / 20, k = idx - pr * 20;
                    int p = pa[pr], q = qa[pr];
                    float c = cs[pr], s = sn[pr];
                    float apk = S[p][k], aqk = S[q][k];
                    S[p][k] = c * apk - s * aqk;
                    S[q][k] = s * apk + c * aqk;
                }
            }
            __syncthreads();
        }
    }

    if (tid < 20) lw[tid] = logf(fmaxf(S[tid][tid], 1e-4f));
    __syncthreads();

    if (tid < 32) {
        float o0 = 0.f, o1 = 0.f, o2 = 0.f, o3 = 0.f;
        const float SQ2 = 1.41421356237309515f;
        for (int p = tid; p < NPAIR; p += 32) {
            int i = 0, rem = p;
            while (rem >= 20 - i) { rem -= 20 - i; ++i; }
            int j = i + rem;
            float L = 0.f;
            #pragma unroll
            for (int mm = 0; mm < 20; ++mm) L += U[i][mm] * lw[mm] * U[j][mm];
            float z = L * ((i == j) ? 1.f : SQ2);
            o0 += z * clf_w[0 * NPAIR + p];
            o1 += z * clf_w[1 * NPAIR + p];
            o2 += z * clf_w[2 * NPAIR + p];
            o3 += z * clf_w[3 * NPAIR + p];
        }
        #pragma unroll
        for (int off = 16; off; off >>= 1) {
            o0 += __shfl_down_sync(0xffffffffu, o0, off);
            o1 += __shfl_down_sync(0xffffffffu, o1, off);
            o2 += __shfl_down_sync(0xffffffffu, o2, off);
            o3 += __shfl_down_sync(0xffffffffu, o3, off);
        }
        if (tid == 0) {
            out[b * 4 + 0] = o0 + clf_b[0];
            out[b * 4 + 1] = o1 + clf_b[1];
            out[b * 4 + 2] = o2 + clf_b[2];
            out[b * 4 + 3] = o3 + clf_b[3];
        }
    }
}

// ---------------------------------------------------------------------------
extern "C" void kernel_launch(void* const* d_in, const int* in_sizes, int n_in,
                              void* d_out, int out_size) {
    const float* x       = (const float*)d_in[0];
    const float* conv1_w = (const float*)d_in[1];
    const float* conv2_w = (const float*)d_in[3];
    const float* W_bimap = (const float*)d_in[5];
    const float* clf_w   = (const float*)d_in[6];
    const float* clf_b   = (const float*)d_in[7];
    float* out = (float*)d_out;

    prep_kernel<<<10, 256>>>(conv2_w, W_bimap);
    gemm_kernel<<<dim3(NCHUNK, BB), 128>>>(x);
    conv_cov_kernel<<<dim3(NCHUNK, BB), 128>>>(conv1_w);
    eig_kernel<<<BB, 64>>>(clf_w, clf_b, out);
}